// round 11
// baseline (speedup 1.0000x reference)
#include <cuda_runtime.h>
#include <cuda_fp16.h>
#include <cstdint>

#define NN 50000
#define EE 800000
#define SCAN_T 2048

// ---------------- scratch (__device__ globals; allocation-free) ----------------
__device__ __half g_h[NN * 128];       // activations fp16 (gather-side)
__device__ __half g_agg[NN * 128];     // SpMM result fp16 (GEMM input)
__device__ float  g_nsrc[NN];
__device__ float  g_ndst[NN];
__device__ __align__(16) int g_dego[NN];
__device__ __align__(16) int g_degi[NN];
__device__ int    g_off[NN + 1];
__device__ int    g_cur[NN];
__device__ int    g_csr[EE];
__device__ int    g_tsum[SCAN_T];
__device__ uint2  g_wfrag[3 * 4096 + 2048];   // HMMA B-frags: 3 layers + proj

// ---------------- f32x2 packed helpers (Blackwell) ----------------
__device__ __forceinline__ unsigned long long pack2(float a, float b) {
    unsigned long long r;
    asm("mov.b64 %0, {%1, %2};" : "=l"(r) : "f"(a), "f"(b));
    return r;
}
__device__ __forceinline__ void unpack2(unsigned long long v, float& a, float& b) {
    asm("mov.b64 {%0, %1}, %2;" : "=f"(a), "=f"(b) : "l"(v));
}
__device__ __forceinline__ void addx2(unsigned long long& acc, unsigned long long v) {
    asm("add.rn.f32x2 %0, %0, %1;" : "+l"(acc) : "l"(v));
}
// accumulate a 16-byte fp16 chunk (8 halves) into 4 f32x2 accumulators
__device__ __forceinline__ void acc_u4(unsigned long long& A0, unsigned long long& A1,
                                       unsigned long long& A2, unsigned long long& A3,
                                       uint4 v) {
    float2 f;
    f = __half22float2(*(const __half2*)&v.x); addx2(A0, pack2(f.x, f.y));
    f = __half22float2(*(const __half2*)&v.y); addx2(A1, pack2(f.x, f.y));
    f = __half22float2(*(const __half2*)&v.z); addx2(A2, pack2(f.x, f.y));
    f = __half22float2(*(const __half2*)&v.w); addx2(A3, pack2(f.x, f.y));
}

// mma.sync m16n8k16 row.col f16*f16+f32
__device__ __forceinline__ void hmma(float* c, uint32_t a0, uint32_t a1, uint32_t a2,
                                     uint32_t a3, uint32_t b0, uint32_t b1) {
    asm volatile(
        "mma.sync.aligned.m16n8k16.row.col.f32.f16.f16.f32 "
        "{%0,%1,%2,%3}, {%4,%5,%6,%7}, {%8,%9}, {%0,%1,%2,%3};"
        : "+f"(c[0]), "+f"(c[1]), "+f"(c[2]), "+f"(c[3])
        : "r"(a0), "r"(a1), "r"(a2), "r"(a3), "r"(b0), "r"(b1));
}

// ---------------- prep: weight frags + zero degree counters (merged) ----------------
// i < 12288: layer frags; 12288..14336: proj frags; i < 12500: zero deg arrays (int4)
__global__ void prep_kernel(const float* __restrict__ Wp, const float* __restrict__ Wl,
                            uint2* __restrict__ frag, int4* dego4, int4* degi4) {
    int i = blockIdx.x * blockDim.x + threadIdx.x;
    if (i < 12500) {
        int4 z = make_int4(0, 0, 0, 0);
        dego4[i] = z;
        degi4[i] = z;
    }
    if (i >= 3 * 4096 + 2048) return;
    const float* W;
    int lane, nt, kt;
    if (i < 12288) {
        lane = i & 31;
        nt = (i >> 5) & 15;
        kt = (i >> 9) & 7;
        W = Wl + (i >> 12) * 16384;
    } else {
        int j = i - 12288;
        lane = j & 31;
        nt = (j >> 5) & 15;
        kt = j >> 9;          // 0..3
        W = Wp;
    }
    int n = nt * 8 + (lane >> 2);
    int k0 = kt * 16 + (lane & 3) * 2;
    __half2 b0 = __floats2half2_rn(W[k0 * 128 + n], W[(k0 + 1) * 128 + n]);
    __half2 b1 = __floats2half2_rn(W[(k0 + 8) * 128 + n], W[(k0 + 9) * 128 + n]);
    uint2 u;
    u.x = *(uint32_t*)&b0;
    u.y = *(uint32_t*)&b1;
    frag[i] = u;
}

// ---------------- CSR build ----------------
__global__ void degree_kernel(const int* __restrict__ src, const int* __restrict__ dst,
                              int* dego, int* degi, int E) {
    int i = blockIdx.x * blockDim.x + threadIdx.x;
    int E4 = E >> 2;
    if (i < E4) {
        int4 s = __ldg((const int4*)src + i);
        int4 d = __ldg((const int4*)dst + i);
        atomicAdd(&dego[s.x], 1);
        atomicAdd(&dego[s.y], 1);
        atomicAdd(&dego[s.z], 1);
        atomicAdd(&dego[s.w], 1);
        atomicAdd(&degi[d.x], 1);
        atomicAdd(&degi[d.y], 1);
        atomicAdd(&degi[d.z], 1);
        atomicAdd(&degi[d.w], 1);
    }
    if (i == 0) {
        for (int e = E4 << 2; e < E; e++) {
            atomicAdd(&dego[src[e]], 1);
            atomicAdd(&degi[dst[e]], 1);
        }
    }
}

__global__ void partsum_kernel(const int* __restrict__ degi, int* tsum, int N) {
    int t = blockIdx.x * blockDim.x + threadIdx.x;
    if (t >= SCAN_T) return;
    int chunk = (N + SCAN_T - 1) / SCAN_T;
    int b = t * chunk, e = min(b + chunk, N);
    int s0 = 0, s1 = 0, s2 = 0, s3 = 0, s4 = 0;
    int i = b;
    for (; i + 5 <= e; i += 5) {
        s0 += degi[i];
        s1 += degi[i + 1];
        s2 += degi[i + 2];
        s3 += degi[i + 3];
        s4 += degi[i + 4];
    }
    for (; i < e; i++) s0 += degi[i];
    tsum[t] = s0 + s1 + s2 + s3 + s4;
}

__global__ void scanpart_kernel(int* tsum) {
    __shared__ int warpsum[32];
    int t = threadIdx.x;
    int lane = t & 31, wid = t >> 5;
    int a = tsum[2 * t], b = tsum[2 * t + 1];
    int v = a + b;
    int inc = v;
    #pragma unroll
    for (int d = 1; d < 32; d <<= 1) {
        int u = __shfl_up_sync(0xffffffffu, inc, d);
        if (lane >= d) inc += u;
    }
    if (lane == 31) warpsum[wid] = inc;
    __syncthreads();
    if (wid == 0) {
        int w = warpsum[lane];
        int wi = w;
        #pragma unroll
        for (int d = 1; d < 32; d <<= 1) {
            int u = __shfl_up_sync(0xffffffffu, wi, d);
            if (lane >= d) wi += u;
        }
        warpsum[lane] = wi - w;
    }
    __syncthreads();
    int excl = inc - v + warpsum[wid];
    tsum[2 * t] = excl;
    tsum[2 * t + 1] = excl + a;
}

__global__ void writeoff_kernel(const int* __restrict__ degi, const int* __restrict__ dego,
                                const int* __restrict__ tsum,
                                int* off, int* cur, float* nsrc, float* ndst, int N) {
    int t = blockIdx.x * blockDim.x + threadIdx.x;
    if (t >= SCAN_T) return;
    int chunk = (N + SCAN_T - 1) / SCAN_T;
    int b = t * chunk, e = min(b + chunk, N);
    int run = tsum[t];
    for (int i = b; i < e; i++) {
        off[i] = run;
        cur[i] = run;
        int di = degi[i];
        run += di;
        ndst[i] = rsqrtf((float)max(di, 1));
        nsrc[i] = rsqrtf((float)max(dego[i], 1));
    }
    if (t == SCAN_T - 1) off[N] = run;
}

__global__ void fill_kernel(const int* __restrict__ src, const int* __restrict__ dst,
                            int* cur, int* csr, int E) {
    int i = blockIdx.x * blockDim.x + threadIdx.x;
    int E4 = E >> 2;
    if (i < E4) {
        int4 s = __ldg((const int4*)src + i);
        int4 d = __ldg((const int4*)dst + i);
        int p0 = atomicAdd(&cur[d.x], 1);
        int p1 = atomicAdd(&cur[d.y], 1);
        int p2 = atomicAdd(&cur[d.z], 1);
        int p3 = atomicAdd(&cur[d.w], 1);
        csr[p0] = s.x;
        csr[p1] = s.y;
        csr[p2] = s.z;
        csr[p3] = s.w;
    }
    if (i == 0) {
        for (int e = E4 << 2; e < E; e++) {
            int p = atomicAdd(&cur[dst[e]], 1);
            csr[p] = src[e];
        }
    }
}

// ---------------- pull SpMM: agg[d] = fp16( ndst[d] * sum_{s in in(d)} h[s] ) -----------
// One warp per dst node; the warp's two 16-lane halves gather DIFFERENT edges with
// LDG.128 (uint4 = 16B = 8 cols per lane). Cross-half combine via shfl_xor(16).
__global__ void pull_kernel(const int* __restrict__ off, const int* __restrict__ csr,
                            const float* __restrict__ ndst,
                            const uint4* __restrict__ h4, uint4* __restrict__ agg4, int N) {
    int w = (blockIdx.x * blockDim.x + threadIdx.x) >> 5;
    int lane = threadIdx.x & 31;
    int half = lane >> 4;
    int sub = lane & 15;
    if (w >= N) return;
    int beg = __ldg(&off[w]);
    int end = __ldg(&off[w + 1]);

    unsigned long long A0 = pack2(0.f, 0.f), A1 = A0, A2 = A0, A3 = A0;

    int j = beg;
    // 8 edges per iteration: 4 LDG.128 in flight, each serving 2 edges
    for (; j + 8 <= end; j += 8) {
        int s0 = __ldg(&csr[j + half]);
        int s1 = __ldg(&csr[j + 2 + half]);
        int s2 = __ldg(&csr[j + 4 + half]);
        int s3 = __ldg(&csr[j + 6 + half]);
        uint4 v0 = __ldg(&h4[(long)s0 * 16 + sub]);
        uint4 v1 = __ldg(&h4[(long)s1 * 16 + sub]);
        uint4 v2 = __ldg(&h4[(long)s2 * 16 + sub]);
        uint4 v3 = __ldg(&h4[(long)s3 * 16 + sub]);
        acc_u4(A0, A1, A2, A3, v0);
        acc_u4(A0, A1, A2, A3, v1);
        acc_u4(A0, A1, A2, A3, v2);
        acc_u4(A0, A1, A2, A3, v3);
    }
    // tail: pairs, predicated per half
    for (; j < end; j += 2) {
        int jj = j + half;
        uint4 v = make_uint4(0u, 0u, 0u, 0u);
        if (jj < end) {
            int s = __ldg(&csr[jj]);
            v = __ldg(&h4[(long)s * 16 + sub]);
        }
        acc_u4(A0, A1, A2, A3, v);
    }

    // combine the two halves (warp-uniform control flow -> all lanes present)
    float f[8];
    unpack2(A0, f[0], f[1]);
    unpack2(A1, f[2], f[3]);
    unpack2(A2, f[4], f[5]);
    unpack2(A3, f[6], f[7]);
    #pragma unroll
    for (int k = 0; k < 8; k++)
        f[k] += __shfl_xor_sync(0xffffffffu, f[k], 16);

    if (half == 0) {
        float nd = __ldg(&ndst[w]);
        __half2 p0 = __floats2half2_rn(f[0] * nd, f[1] * nd);
        __half2 p1 = __floats2half2_rn(f[2] * nd, f[3] * nd);
        __half2 p2 = __floats2half2_rn(f[4] * nd, f[5] * nd);
        __half2 p3 = __floats2half2_rn(f[6] * nd, f[7] * nd);
        uint4 st;
        st.x = *(uint32_t*)&p0;
        st.y = *(uint32_t*)&p1;
        st.z = *(uint32_t*)&p2;
        st.w = *(uint32_t*)&p3;
        agg4[(long)w * 16 + sub] = st;
    }
}

// ---------------- HMMA GEMM: out = relu(X @ W + bias) * postscale ----------------
template <int KTILES, bool FP32IN, bool HALF_OUT>
__global__ void __launch_bounds__(256, 2)
gemm_mma_kernel(const void* __restrict__ Xv, const uint2* __restrict__ Wfrag,
                const float* __restrict__ B, const float* __restrict__ postscale,
                void* __restrict__ outv, int n) {
    constexpr int XPADH = KTILES * 16 + 8;
    constexpr int C4 = KTILES * 4;
    extern __shared__ char smraw[];
    __half* x_sh = (__half*)smraw;
    uint2* w_sh = (uint2*)(smraw + 128 * XPADH * 2);

    const int tx = threadIdx.x;
    const int row0 = blockIdx.x * 128;

    #pragma unroll
    for (int i = tx; i < KTILES * 512; i += 256) w_sh[i] = __ldg(&Wfrag[i]);

    #pragma unroll
    for (int i = tx; i < 128 * C4; i += 256) {
        int r = i / C4, c = i % C4;
        int gr = row0 + r;
        if (gr >= n) gr = n - 1;
        uint2 v;
        if (FP32IN) {
            float4 f = __ldg((const float4*)Xv + (long)gr * C4 + c);
            __half2 h0 = __floats2half2_rn(f.x, f.y);
            __half2 h1 = __floats2half2_rn(f.z, f.w);
            v.x = *(uint32_t*)&h0;
            v.y = *(uint32_t*)&h1;
        } else {
            v = __ldg((const uint2*)Xv + (long)gr * C4 + c);
        }
        *(uint2*)&x_sh[r * XPADH + c * 4] = v;
    }
    __syncthreads();

    const int w = tx >> 5;
    const int lane = tx & 31;
    const int rq = lane >> 2;
    const int kq = (lane & 3) * 2;

    float c[16][4];
    #pragma unroll
    for (int nt = 0; nt < 16; nt++)
        #pragma unroll
        for (int q = 0; q < 4; q++) c[nt][q] = 0.0f;

    #pragma unroll
    for (int kt = 0; kt < KTILES; kt++) {
        const __half* arow0 = &x_sh[(w * 16 + rq) * XPADH + kt * 16 + kq];
        const __half* arow1 = arow0 + 8 * XPADH;
        uint32_t a0 = *(const uint32_t*)arow0;
        uint32_t a1 = *(const uint32_t*)arow1;
        uint32_t a2 = *(const uint32_t*)(arow0 + 8);
        uint32_t a3 = *(const uint32_t*)(arow1 + 8);
        #pragma unroll
        for (int nt = 0; nt < 16; nt++) {
            uint2 b = w_sh[(kt * 16 + nt) * 32 + lane];
            hmma(c[nt], a0, a1, a2, a3, b.x, b.y);
        }
    }

    int r0 = row0 + w * 16 + rq;
    int r1 = r0 + 8;
    float sc0 = 1.0f, sc1 = 1.0f;
    if (postscale) {
        if (r0 < n) sc0 = __ldg(&postscale[r0]);
        if (r1 < n) sc1 = __ldg(&postscale[r1]);
    }
    #pragma unroll
    for (int nt = 0; nt < 16; nt++) {
        int col = nt * 8 + kq;
        float2 bv = *(const float2*)&B[col];
        float o00 = fmaxf(c[nt][0] + bv.x, 0.0f) * sc0;
        float o01 = fmaxf(c[nt][1] + bv.y, 0.0f) * sc0;
        float o10 = fmaxf(c[nt][2] + bv.x, 0.0f) * sc1;
        float o11 = fmaxf(c[nt][3] + bv.y, 0.0f) * sc1;
        if (HALF_OUT) {
            if (r0 < n) {
                __half2 p = __floats2half2_rn(o00, o01);
                *(uint32_t*)((__half*)outv + (long)r0 * 128 + col) = *(uint32_t*)&p;
            }
            if (r1 < n) {
                __half2 p = __floats2half2_rn(o10, o11);
                *(uint32_t*)((__half*)outv + (long)r1 * 128 + col) = *(uint32_t*)&p;
            }
        } else {
            if (r0 < n)
                *(float2*)((float*)outv + (long)r0 * 128 + col) = make_float2(o00, o01);
            if (r1 < n)
                *(float2*)((float*)outv + (long)r1 * 128 + col) = make_float2(o10, o11);
        }
    }
}

extern "C" void kernel_launch(void* const* d_in, const int* in_sizes, int n_in,
                              void* d_out, int out_size) {
    const float* x_raw = (const float*)d_in[0];
    const int*   src   = (const int*)d_in[1];
    const int*   dst   = (const int*)d_in[2];
    const float* Wp    = (const float*)d_in[3];
    const float* bp    = (const float*)d_in[4];
    const float* Wl    = (const float*)d_in[5];
    const float* bl    = (const float*)d_in[6];
    float* out = (float*)d_out;

    const int N = in_sizes[0] / 64;
    const int E = in_sizes[1];

    __half *h, *agg;
    float *nsrc, *ndst;
    int *dego, *degi, *off, *cur, *csr, *tsum;
    uint2* wfrag;
    cudaGetSymbolAddress((void**)&h, g_h);
    cudaGetSymbolAddress((void**)&agg, g_agg);
    cudaGetSymbolAddress((void**)&nsrc, g_nsrc);
    cudaGetSymbolAddress((void**)&ndst, g_ndst);
    cudaGetSymbolAddress((void**)&dego, g_dego);
    cudaGetSymbolAddress((void**)&degi, g_degi);
    cudaGetSymbolAddress((void**)&off, g_off);
    cudaGetSymbolAddress((void**)&cur, g_cur);
    cudaGetSymbolAddress((void**)&csr, g_csr);
    cudaGetSymbolAddress((void**)&tsum, g_tsum);
    cudaGetSymbolAddress((void**)&wfrag, g_wfrag);

    const int MMA_SMEM128 = 128 * 136 * 2 + 4096 * 8;
    const int MMA_SMEM64 = 128 * 72 * 2 + 2048 * 8;
    cudaFuncSetAttribute((const void*)gemm_mma_kernel<8, false, true>,
                         cudaFuncAttributeMaxDynamicSharedMemorySize, MMA_SMEM128);
    cudaFuncSetAttribute((const void*)gemm_mma_kernel<8, false, false>,
                         cudaFuncAttributeMaxDynamicSharedMemorySize, MMA_SMEM128);
    cudaFuncSetAttribute((const void*)gemm_mma_kernel<4, true, true>,
                         cudaFuncAttributeMaxDynamicSharedMemorySize, MMA_SMEM64);

    // 0) weight frags + zero degree counters (merged)
    prep_kernel<<<(3 * 4096 + 2048 + 255) / 256, 256>>>(
        Wp, Wl, wfrag, (int4*)dego, (int4*)degi);

    // 1) degrees -> norms + CSR(by dst)
    const int E4 = E >> 2;
    degree_kernel<<<(E4 + 255) / 256, 256>>>(src, dst, dego, degi, E);
    partsum_kernel<<<SCAN_T / 256, 256>>>(degi, tsum, N);
    scanpart_kernel<<<1, 1024>>>(tsum);
    writeoff_kernel<<<SCAN_T / 256, 256>>>(degi, dego, tsum, off, cur, nsrc, ndst, N);
    fill_kernel<<<(E4 + 255) / 256, 256>>>(src, dst, cur, csr, E);

    // 2) h = fp16( relu(x_raw @ Wp + bp) * norm_src )  — HMMA, K=64
    const int mma_blocks = (N + 127) / 128;
    gemm_mma_kernel<4, true, true><<<mma_blocks, 256, MMA_SMEM64>>>(
        x_raw, wfrag + 12288, bp, nsrc, h, N);

    // 3) layers: pull (LDG.128 paired-edge) then HMMA GEMM
    const int pull_blocks = (N * 32 + 255) / 256;
    for (int l = 0; l < 3; l++) {
        pull_kernel<<<pull_blocks, 256>>>(off, csr, ndst, (const uint4*)h, (uint4*)agg, N);
        const uint2* wf = wfrag + (long)l * 4096;
        const float* bcur = bl + (long)l * 128;
        if (l == 2) {
            gemm_mma_kernel<8, false, false><<<mma_blocks, 256, MMA_SMEM128>>>(
                (const void*)agg, wf, bcur, nullptr, out, N);
        } else {
            gemm_mma_kernel<8, false, true><<<mma_blocks, 256, MMA_SMEM128>>>(
                (const void*)agg, wf, bcur, nsrc, h, N);
        }
    }
}

// round 12
// speedup vs baseline: 1.0510x; 1.0510x over previous
#include <cuda_runtime.h>
#include <cuda_fp16.h>
#include <cstdint>

#define NN 50000
#define EE 800000
#define SCAN_T 2048

// ---------------- scratch (__device__ globals; allocation-free) ----------------
__device__ __half g_h[NN * 128];       // activations fp16 (gather-side)
__device__ __half g_agg[NN * 128];     // SpMM result fp16 (GEMM input)
__device__ float  g_nsrc[NN];
__device__ float  g_ndst[NN];
__device__ __align__(16) int g_dego[NN];
__device__ __align__(16) int g_degi[NN];
__device__ int    g_off[NN + 1];
__device__ int    g_cur[NN];
__device__ int    g_csr[EE];
__device__ int    g_tsum[SCAN_T];
__device__ uint2  g_wfrag[3 * 4096 + 2048];   // HMMA B-frags: 3 layers + proj

// ---------------- f32x2 packed helpers (Blackwell) ----------------
__device__ __forceinline__ unsigned long long pack2(float a, float b) {
    unsigned long long r;
    asm("mov.b64 %0, {%1, %2};" : "=l"(r) : "f"(a), "f"(b));
    return r;
}
__device__ __forceinline__ void unpack2(unsigned long long v, float& a, float& b) {
    asm("mov.b64 {%0, %1}, %2;" : "=f"(a), "=f"(b) : "l"(v));
}
__device__ __forceinline__ void addx2(unsigned long long& acc, unsigned long long v) {
    asm("add.rn.f32x2 %0, %0, %1;" : "+l"(acc) : "l"(v));
}
__device__ __forceinline__ void mulx2(unsigned long long& acc, unsigned long long v) {
    asm("mul.rn.f32x2 %0, %0, %1;" : "+l"(acc) : "l"(v));
}
__device__ __forceinline__ void acc_h2(unsigned long long& a0, unsigned long long& a1,
                                       uint2 v) {
    float2 f;
    f = __half22float2(*(const __half2*)&v.x);
    addx2(a0, pack2(f.x, f.y));
    f = __half22float2(*(const __half2*)&v.y);
    addx2(a1, pack2(f.x, f.y));
}

// mma.sync m16n8k16 row.col f16*f16+f32
__device__ __forceinline__ void hmma(float* c, uint32_t a0, uint32_t a1, uint32_t a2,
                                     uint32_t a3, uint32_t b0, uint32_t b1) {
    asm volatile(
        "mma.sync.aligned.m16n8k16.row.col.f32.f16.f16.f32 "
        "{%0,%1,%2,%3}, {%4,%5,%6,%7}, {%8,%9}, {%0,%1,%2,%3};"
        : "+f"(c[0]), "+f"(c[1]), "+f"(c[2]), "+f"(c[3])
        : "r"(a0), "r"(a1), "r"(a2), "r"(a3), "r"(b0), "r"(b1));
}

// ---------------- prep: weight frags + zero degree counters (merged) ----------------
__global__ void prep_kernel(const float* __restrict__ Wp, const float* __restrict__ Wl,
                            uint2* __restrict__ frag, int4* dego4, int4* degi4) {
    int i = blockIdx.x * blockDim.x + threadIdx.x;
    if (i < 12500) {
        int4 z = make_int4(0, 0, 0, 0);
        dego4[i] = z;
        degi4[i] = z;
    }
    if (i >= 3 * 4096 + 2048) return;
    const float* W;
    int lane, nt, kt;
    if (i < 12288) {
        lane = i & 31;
        nt = (i >> 5) & 15;
        kt = (i >> 9) & 7;
        W = Wl + (i >> 12) * 16384;
    } else {
        int j = i - 12288;
        lane = j & 31;
        nt = (j >> 5) & 15;
        kt = j >> 9;          // 0..3
        W = Wp;
    }
    int n = nt * 8 + (lane >> 2);
    int k0 = kt * 16 + (lane & 3) * 2;
    __half2 b0 = __floats2half2_rn(W[k0 * 128 + n], W[(k0 + 1) * 128 + n]);
    __half2 b1 = __floats2half2_rn(W[(k0 + 8) * 128 + n], W[(k0 + 9) * 128 + n]);
    uint2 u;
    u.x = *(uint32_t*)&b0;
    u.y = *(uint32_t*)&b1;
    frag[i] = u;
}

// ---------------- CSR build ----------------
// 8 edges per thread (2x int4) for atomic MLP.
__global__ void degree_kernel(const int* __restrict__ src, const int* __restrict__ dst,
                              int* dego, int* degi, int E) {
    int i = blockIdx.x * blockDim.x + threadIdx.x;
    int E8 = E >> 3;
    if (i < E8) {
        int4 sa = __ldg((const int4*)src + 2 * i);
        int4 sb = __ldg((const int4*)src + 2 * i + 1);
        int4 da = __ldg((const int4*)dst + 2 * i);
        int4 db = __ldg((const int4*)dst + 2 * i + 1);
        atomicAdd(&dego[sa.x], 1);
        atomicAdd(&dego[sa.y], 1);
        atomicAdd(&dego[sa.z], 1);
        atomicAdd(&dego[sa.w], 1);
        atomicAdd(&dego[sb.x], 1);
        atomicAdd(&dego[sb.y], 1);
        atomicAdd(&dego[sb.z], 1);
        atomicAdd(&dego[sb.w], 1);
        atomicAdd(&degi[da.x], 1);
        atomicAdd(&degi[da.y], 1);
        atomicAdd(&degi[da.z], 1);
        atomicAdd(&degi[da.w], 1);
        atomicAdd(&degi[db.x], 1);
        atomicAdd(&degi[db.y], 1);
        atomicAdd(&degi[db.z], 1);
        atomicAdd(&degi[db.w], 1);
    }
    if (i == 0) {
        for (int e = E8 << 3; e < E; e++) {
            atomicAdd(&dego[src[e]], 1);
            atomicAdd(&degi[dst[e]], 1);
        }
    }
}

__global__ void partsum_kernel(const int* __restrict__ degi, int* tsum, int N) {
    int t = blockIdx.x * blockDim.x + threadIdx.x;
    if (t >= SCAN_T) return;
    int chunk = (N + SCAN_T - 1) / SCAN_T;
    int b = t * chunk, e = min(b + chunk, N);
    int s0 = 0, s1 = 0, s2 = 0, s3 = 0, s4 = 0;
    int i = b;
    for (; i + 5 <= e; i += 5) {
        s0 += degi[i];
        s1 += degi[i + 1];
        s2 += degi[i + 2];
        s3 += degi[i + 3];
        s4 += degi[i + 4];
    }
    for (; i < e; i++) s0 += degi[i];
    tsum[t] = s0 + s1 + s2 + s3 + s4;
}

__global__ void scanpart_kernel(int* tsum) {
    __shared__ int warpsum[32];
    int t = threadIdx.x;
    int lane = t & 31, wid = t >> 5;
    int a = tsum[2 * t], b = tsum[2 * t + 1];
    int v = a + b;
    int inc = v;
    #pragma unroll
    for (int d = 1; d < 32; d <<= 1) {
        int u = __shfl_up_sync(0xffffffffu, inc, d);
        if (lane >= d) inc += u;
    }
    if (lane == 31) warpsum[wid] = inc;
    __syncthreads();
    if (wid == 0) {
        int w = warpsum[lane];
        int wi = w;
        #pragma unroll
        for (int d = 1; d < 32; d <<= 1) {
            int u = __shfl_up_sync(0xffffffffu, wi, d);
            if (lane >= d) wi += u;
        }
        warpsum[lane] = wi - w;
    }
    __syncthreads();
    int excl = inc - v + warpsum[wid];
    tsum[2 * t] = excl;
    tsum[2 * t + 1] = excl + a;
}

__global__ void writeoff_kernel(const int* __restrict__ degi, const int* __restrict__ dego,
                                const int* __restrict__ tsum,
                                int* off, int* cur, float* nsrc, float* ndst, int N) {
    int t = blockIdx.x * blockDim.x + threadIdx.x;
    if (t >= SCAN_T) return;
    int chunk = (N + SCAN_T - 1) / SCAN_T;
    int b = t * chunk, e = min(b + chunk, N);
    int run = tsum[t];
    for (int i = b; i < e; i++) {
        off[i] = run;
        cur[i] = run;
        int di = degi[i];
        run += di;
        ndst[i] = rsqrtf((float)max(di, 1));
        nsrc[i] = rsqrtf((float)max(dego[i], 1));
    }
    if (t == SCAN_T - 1) off[N] = run;
}

// 8 edges per thread: 8 independent ATOMG returns in flight.
__global__ void fill_kernel(const int* __restrict__ src, const int* __restrict__ dst,
                            int* cur, int* csr, int E) {
    int i = blockIdx.x * blockDim.x + threadIdx.x;
    int E8 = E >> 3;
    if (i < E8) {
        int4 sa = __ldg((const int4*)src + 2 * i);
        int4 sb = __ldg((const int4*)src + 2 * i + 1);
        int4 da = __ldg((const int4*)dst + 2 * i);
        int4 db = __ldg((const int4*)dst + 2 * i + 1);
        int p0 = atomicAdd(&cur[da.x], 1);
        int p1 = atomicAdd(&cur[da.y], 1);
        int p2 = atomicAdd(&cur[da.z], 1);
        int p3 = atomicAdd(&cur[da.w], 1);
        int p4 = atomicAdd(&cur[db.x], 1);
        int p5 = atomicAdd(&cur[db.y], 1);
        int p6 = atomicAdd(&cur[db.z], 1);
        int p7 = atomicAdd(&cur[db.w], 1);
        csr[p0] = sa.x;
        csr[p1] = sa.y;
        csr[p2] = sa.z;
        csr[p3] = sa.w;
        csr[p4] = sb.x;
        csr[p5] = sb.y;
        csr[p6] = sb.z;
        csr[p7] = sb.w;
    }
    if (i == 0) {
        for (int e = E8 << 3; e < E; e++) {
            int p = atomicAdd(&cur[dst[e]], 1);
            csr[p] = src[e];
        }
    }
}

// ---------------- pull SpMM (R10 version): agg[d] = fp16( ndst[d] * sum h[s] ) ----------
__global__ void pull_kernel(const int* __restrict__ off, const int* __restrict__ csr,
                            const float* __restrict__ ndst,
                            const uint2* __restrict__ h2, uint2* __restrict__ agg2, int N) {
    int w = (blockIdx.x * blockDim.x + threadIdx.x) >> 5;
    int lane = threadIdx.x & 31;
    if (w >= N) return;
    int beg = __ldg(&off[w]);
    int end = __ldg(&off[w + 1]);

    unsigned long long a0 = pack2(0.f, 0.f), a1 = a0, b0 = a0, b1 = a0;

    int j = beg;
    for (; j + 8 <= end; j += 8) {
        int s0 = __ldg(&csr[j]);
        int s1 = __ldg(&csr[j + 1]);
        int s2 = __ldg(&csr[j + 2]);
        int s3 = __ldg(&csr[j + 3]);
        int s4 = __ldg(&csr[j + 4]);
        int s5 = __ldg(&csr[j + 5]);
        int s6 = __ldg(&csr[j + 6]);
        int s7 = __ldg(&csr[j + 7]);
        uint2 v0 = __ldg(&h2[(long)s0 * 32 + lane]);
        uint2 v1 = __ldg(&h2[(long)s1 * 32 + lane]);
        uint2 v2 = __ldg(&h2[(long)s2 * 32 + lane]);
        uint2 v3 = __ldg(&h2[(long)s3 * 32 + lane]);
        uint2 v4 = __ldg(&h2[(long)s4 * 32 + lane]);
        uint2 v5 = __ldg(&h2[(long)s5 * 32 + lane]);
        uint2 v6 = __ldg(&h2[(long)s6 * 32 + lane]);
        uint2 v7 = __ldg(&h2[(long)s7 * 32 + lane]);
        acc_h2(a0, a1, v0);
        acc_h2(b0, b1, v1);
        acc_h2(a0, a1, v2);
        acc_h2(b0, b1, v3);
        acc_h2(a0, a1, v4);
        acc_h2(b0, b1, v5);
        acc_h2(a0, a1, v6);
        acc_h2(b0, b1, v7);
    }
    for (; j < end; j++) {
        int s = __ldg(&csr[j]);
        acc_h2(a0, a1, __ldg(&h2[(long)s * 32 + lane]));
    }
    addx2(a0, b0);
    addx2(a1, b1);

    float nd = __ldg(&ndst[w]);
    unsigned long long nn = pack2(nd, nd);
    mulx2(a0, nn);
    mulx2(a1, nn);
    float4 o;
    unpack2(a0, o.x, o.y);
    unpack2(a1, o.z, o.w);
    __half2 p0 = __floats2half2_rn(o.x, o.y);
    __half2 p1 = __floats2half2_rn(o.z, o.w);
    uint2 st;
    st.x = *(uint32_t*)&p0;
    st.y = *(uint32_t*)&p1;
    agg2[(long)w * 32 + lane] = st;
}

// ---------------- HMMA GEMM: out = relu(X @ W + bias) * postscale ----------------
template <int KTILES, bool FP32IN, bool HALF_OUT>
__global__ void __launch_bounds__(256, 2)
gemm_mma_kernel(const void* __restrict__ Xv, const uint2* __restrict__ Wfrag,
                const float* __restrict__ B, const float* __restrict__ postscale,
                void* __restrict__ outv, int n) {
    constexpr int XPADH = KTILES * 16 + 8;
    constexpr int C4 = KTILES * 4;
    extern __shared__ char smraw[];
    __half* x_sh = (__half*)smraw;
    uint2* w_sh = (uint2*)(smraw + 128 * XPADH * 2);

    const int tx = threadIdx.x;
    const int row0 = blockIdx.x * 128;

    #pragma unroll
    for (int i = tx; i < KTILES * 512; i += 256) w_sh[i] = __ldg(&Wfrag[i]);

    #pragma unroll
    for (int i = tx; i < 128 * C4; i += 256) {
        int r = i / C4, c = i % C4;
        int gr = row0 + r;
        if (gr >= n) gr = n - 1;
        uint2 v;
        if (FP32IN) {
            float4 f = __ldg((const float4*)Xv + (long)gr * C4 + c);
            __half2 h0 = __floats2half2_rn(f.x, f.y);
            __half2 h1 = __floats2half2_rn(f.z, f.w);
            v.x = *(uint32_t*)&h0;
            v.y = *(uint32_t*)&h1;
        } else {
            v = __ldg((const uint2*)Xv + (long)gr * C4 + c);
        }
        *(uint2*)&x_sh[r * XPADH + c * 4] = v;
    }
    __syncthreads();

    const int w = tx >> 5;
    const int lane = tx & 31;
    const int rq = lane >> 2;
    const int kq = (lane & 3) * 2;

    float c[16][4];
    #pragma unroll
    for (int nt = 0; nt < 16; nt++)
        #pragma unroll
        for (int q = 0; q < 4; q++) c[nt][q] = 0.0f;

    #pragma unroll
    for (int kt = 0; kt < KTILES; kt++) {
        const __half* arow0 = &x_sh[(w * 16 + rq) * XPADH + kt * 16 + kq];
        const __half* arow1 = arow0 + 8 * XPADH;
        uint32_t a0 = *(const uint32_t*)arow0;
        uint32_t a1 = *(const uint32_t*)arow1;
        uint32_t a2 = *(const uint32_t*)(arow0 + 8);
        uint32_t a3 = *(const uint32_t*)(arow1 + 8);
        #pragma unroll
        for (int nt = 0; nt < 16; nt++) {
            uint2 b = w_sh[(kt * 16 + nt) * 32 + lane];
            hmma(c[nt], a0, a1, a2, a3, b.x, b.y);
        }
    }

    int r0 = row0 + w * 16 + rq;
    int r1 = r0 + 8;
    float sc0 = 1.0f, sc1 = 1.0f;
    if (postscale) {
        if (r0 < n) sc0 = __ldg(&postscale[r0]);
        if (r1 < n) sc1 = __ldg(&postscale[r1]);
    }
    #pragma unroll
    for (int nt = 0; nt < 16; nt++) {
        int col = nt * 8 + kq;
        float2 bv = *(const float2*)&B[col];
        float o00 = fmaxf(c[nt][0] + bv.x, 0.0f) * sc0;
        float o01 = fmaxf(c[nt][1] + bv.y, 0.0f) * sc0;
        float o10 = fmaxf(c[nt][2] + bv.x, 0.0f) * sc1;
        float o11 = fmaxf(c[nt][3] + bv.y, 0.0f) * sc1;
        if (HALF_OUT) {
            if (r0 < n) {
                __half2 p = __floats2half2_rn(o00, o01);
                *(uint32_t*)((__half*)outv + (long)r0 * 128 + col) = *(uint32_t*)&p;
            }
            if (r1 < n) {
                __half2 p = __floats2half2_rn(o10, o11);
                *(uint32_t*)((__half*)outv + (long)r1 * 128 + col) = *(uint32_t*)&p;
            }
        } else {
            if (r0 < n)
                *(float2*)((float*)outv + (long)r0 * 128 + col) = make_float2(o00, o01);
            if (r1 < n)
                *(float2*)((float*)outv + (long)r1 * 128 + col) = make_float2(o10, o11);
        }
    }
}

extern "C" void kernel_launch(void* const* d_in, const int* in_sizes, int n_in,
                              void* d_out, int out_size) {
    const float* x_raw = (const float*)d_in[0];
    const int*   src   = (const int*)d_in[1];
    const int*   dst   = (const int*)d_in[2];
    const float* Wp    = (const float*)d_in[3];
    const float* bp    = (const float*)d_in[4];
    const float* Wl    = (const float*)d_in[5];
    const float* bl    = (const float*)d_in[6];
    float* out = (float*)d_out;

    const int N = in_sizes[0] / 64;
    const int E = in_sizes[1];

    __half *h, *agg;
    float *nsrc, *ndst;
    int *dego, *degi, *off, *cur, *csr, *tsum;
    uint2* wfrag;
    cudaGetSymbolAddress((void**)&h, g_h);
    cudaGetSymbolAddress((void**)&agg, g_agg);
    cudaGetSymbolAddress((void**)&nsrc, g_nsrc);
    cudaGetSymbolAddress((void**)&ndst, g_ndst);
    cudaGetSymbolAddress((void**)&dego, g_dego);
    cudaGetSymbolAddress((void**)&degi, g_degi);
    cudaGetSymbolAddress((void**)&off, g_off);
    cudaGetSymbolAddress((void**)&cur, g_cur);
    cudaGetSymbolAddress((void**)&csr, g_csr);
    cudaGetSymbolAddress((void**)&tsum, g_tsum);
    cudaGetSymbolAddress((void**)&wfrag, g_wfrag);

    const int MMA_SMEM128 = 128 * 136 * 2 + 4096 * 8;
    const int MMA_SMEM64 = 128 * 72 * 2 + 2048 * 8;
    cudaFuncSetAttribute((const void*)gemm_mma_kernel<8, false, true>,
                         cudaFuncAttributeMaxDynamicSharedMemorySize, MMA_SMEM128);
    cudaFuncSetAttribute((const void*)gemm_mma_kernel<8, false, false>,
                         cudaFuncAttributeMaxDynamicSharedMemorySize, MMA_SMEM128);
    cudaFuncSetAttribute((const void*)gemm_mma_kernel<4, true, true>,
                         cudaFuncAttributeMaxDynamicSharedMemorySize, MMA_SMEM64);

    // 0) weight frags + zero degree counters (merged)
    prep_kernel<<<(3 * 4096 + 2048 + 255) / 256, 256>>>(
        Wp, Wl, wfrag, (int4*)dego, (int4*)degi);

    // 1) degrees -> norms + CSR(by dst)
    const int E8 = E >> 3;
    degree_kernel<<<(E8 + 255) / 256, 256>>>(src, dst, dego, degi, E);
    partsum_kernel<<<SCAN_T / 256, 256>>>(degi, tsum, N);
    scanpart_kernel<<<1, 1024>>>(tsum);
    writeoff_kernel<<<SCAN_T / 256, 256>>>(degi, dego, tsum, off, cur, nsrc, ndst, N);
    fill_kernel<<<(E8 + 255) / 256, 256>>>(src, dst, cur, csr, E);

    // 2) h = fp16( relu(x_raw @ Wp + bp) * norm_src )  — HMMA, K=64
    const int mma_blocks = (N + 127) / 128;
    gemm_mma_kernel<4, true, true><<<mma_blocks, 256, MMA_SMEM64>>>(
        x_raw, wfrag + 12288, bp, nsrc, h, N);

    // 3) layers: pull then HMMA GEMM
    const int pull_blocks = (N * 32 + 255) / 256;
    for (int l = 0; l < 3; l++) {
        pull_kernel<<<pull_blocks, 256>>>(off, csr, ndst, (const uint2*)h, (uint2*)agg, N);
        const uint2* wf = wfrag + (long)l * 4096;
        const float* bcur = bl + (long)l * 128;
        if (l == 2) {
            gemm_mma_kernel<8, false, false><<<mma_blocks, 256, MMA_SMEM128>>>(
                (const void*)agg, wf, bcur, nullptr, out, N);
        } else {
            gemm_mma_kernel<8, false, true><<<mma_blocks, 256, MMA_SMEM128>>>(
                (const void*)agg, wf, bcur, nsrc, h, N);
        }
    }
}

// round 13
// speedup vs baseline: 1.0547x; 1.0035x over previous
#include <cuda_runtime.h>
#include <cuda_fp16.h>
#include <cstdint>

#define NN 50000
#define EE 800000
#define SCAN_T 2048

// ---------------- scratch (__device__ globals; allocation-free) ----------------
__device__ __half g_h[NN * 128];       // activations fp16 (gather-side)
__device__ __half g_agg[NN * 128];     // SpMM result fp16 (GEMM input)
__device__ float  g_nsrc[NN];
__device__ float  g_ndst[NN];
__device__ __align__(16) int g_dego[NN];
__device__ __align__(16) int g_degi[NN];
__device__ int    g_off[NN + 1];
__device__ int    g_cur[NN];
__device__ int    g_csr[EE];
__device__ int    g_tsum[SCAN_T];
__device__ uint2  g_wfrag[3 * 4096 + 2048];   // HMMA B-frags: 3 layers + proj

// ---------------- f32x2 packed helpers (Blackwell) ----------------
__device__ __forceinline__ unsigned long long pack2(float a, float b) {
    unsigned long long r;
    asm("mov.b64 %0, {%1, %2};" : "=l"(r) : "f"(a), "f"(b));
    return r;
}
__device__ __forceinline__ void unpack2(unsigned long long v, float& a, float& b) {
    asm("mov.b64 {%0, %1}, %2;" : "=f"(a), "=f"(b) : "l"(v));
}
__device__ __forceinline__ void addx2(unsigned long long& acc, unsigned long long v) {
    asm("add.rn.f32x2 %0, %0, %1;" : "+l"(acc) : "l"(v));
}
__device__ __forceinline__ void mulx2(unsigned long long& acc, unsigned long long v) {
    asm("mul.rn.f32x2 %0, %0, %1;" : "+l"(acc) : "l"(v));
}
__device__ __forceinline__ void acc_h2(unsigned long long& a0, unsigned long long& a1,
                                       uint2 v) {
    float2 f;
    f = __half22float2(*(const __half2*)&v.x);
    addx2(a0, pack2(f.x, f.y));
    f = __half22float2(*(const __half2*)&v.y);
    addx2(a1, pack2(f.x, f.y));
}

// mma.sync m16n8k16 row.col f16*f16+f32
__device__ __forceinline__ void hmma(float* c, uint32_t a0, uint32_t a1, uint32_t a2,
                                     uint32_t a3, uint32_t b0, uint32_t b1) {
    asm volatile(
        "mma.sync.aligned.m16n8k16.row.col.f32.f16.f16.f32 "
        "{%0,%1,%2,%3}, {%4,%5,%6,%7}, {%8,%9}, {%0,%1,%2,%3};"
        : "+f"(c[0]), "+f"(c[1]), "+f"(c[2]), "+f"(c[3])
        : "r"(a0), "r"(a1), "r"(a2), "r"(a3), "r"(b0), "r"(b1));
}

// ---------------- prep: weight frags + zero degree counters (merged) ----------------
__global__ void prep_kernel(const float* __restrict__ Wp, const float* __restrict__ Wl,
                            uint2* __restrict__ frag, int4* dego4, int4* degi4) {
    int i = blockIdx.x * blockDim.x + threadIdx.x;
    if (i < 12500) {
        int4 z = make_int4(0, 0, 0, 0);
        dego4[i] = z;
        degi4[i] = z;
    }
    if (i >= 3 * 4096 + 2048) return;
    const float* W;
    int lane, nt, kt;
    if (i < 12288) {
        lane = i & 31;
        nt = (i >> 5) & 15;
        kt = (i >> 9) & 7;
        W = Wl + (i >> 12) * 16384;
    } else {
        int j = i - 12288;
        lane = j & 31;
        nt = (j >> 5) & 15;
        kt = j >> 9;          // 0..3
        W = Wp;
    }
    int n = nt * 8 + (lane >> 2);
    int k0 = kt * 16 + (lane & 3) * 2;
    __half2 b0 = __floats2half2_rn(W[k0 * 128 + n], W[(k0 + 1) * 128 + n]);
    __half2 b1 = __floats2half2_rn(W[(k0 + 8) * 128 + n], W[(k0 + 9) * 128 + n]);
    uint2 u;
    u.x = *(uint32_t*)&b0;
    u.y = *(uint32_t*)&b1;
    frag[i] = u;
}

// ---------------- CSR build ----------------
// 8 edges per thread (2x int4) for atomic MLP.
__global__ void degree_kernel(const int* __restrict__ src, const int* __restrict__ dst,
                              int* dego, int* degi, int E) {
    int i = blockIdx.x * blockDim.x + threadIdx.x;
    int E8 = E >> 3;
    if (i < E8) {
        int4 sa = __ldg((const int4*)src + 2 * i);
        int4 sb = __ldg((const int4*)src + 2 * i + 1);
        int4 da = __ldg((const int4*)dst + 2 * i);
        int4 db = __ldg((const int4*)dst + 2 * i + 1);
        atomicAdd(&dego[sa.x], 1);
        atomicAdd(&dego[sa.y], 1);
        atomicAdd(&dego[sa.z], 1);
        atomicAdd(&dego[sa.w], 1);
        atomicAdd(&dego[sb.x], 1);
        atomicAdd(&dego[sb.y], 1);
        atomicAdd(&dego[sb.z], 1);
        atomicAdd(&dego[sb.w], 1);
        atomicAdd(&degi[da.x], 1);
        atomicAdd(&degi[da.y], 1);
        atomicAdd(&degi[da.z], 1);
        atomicAdd(&degi[da.w], 1);
        atomicAdd(&degi[db.x], 1);
        atomicAdd(&degi[db.y], 1);
        atomicAdd(&degi[db.z], 1);
        atomicAdd(&degi[db.w], 1);
    }
    if (i == 0) {
        for (int e = E8 << 3; e < E; e++) {
            atomicAdd(&dego[src[e]], 1);
            atomicAdd(&degi[dst[e]], 1);
        }
    }
}

// partial sums of degi per chunk PLUS norm computation (nsrc/ndst)
__global__ void partsum_norm_kernel(const int* __restrict__ degi,
                                    const int* __restrict__ dego,
                                    int* tsum, float* nsrc, float* ndst, int N) {
    int t = blockIdx.x * blockDim.x + threadIdx.x;
    if (t >= SCAN_T) return;
    int chunk = (N + SCAN_T - 1) / SCAN_T;
    int b = t * chunk, e = min(b + chunk, N);
    int s0 = 0, s1 = 0, s2 = 0, s3 = 0, s4 = 0;
    int i = b;
    for (; i + 5 <= e; i += 5) {
        int d0 = degi[i], d1 = degi[i + 1], d2 = degi[i + 2], d3 = degi[i + 3],
            d4 = degi[i + 4];
        int o0 = dego[i], o1 = dego[i + 1], o2 = dego[i + 2], o3 = dego[i + 3],
            o4 = dego[i + 4];
        s0 += d0; s1 += d1; s2 += d2; s3 += d3; s4 += d4;
        ndst[i] = rsqrtf((float)max(d0, 1));
        ndst[i + 1] = rsqrtf((float)max(d1, 1));
        ndst[i + 2] = rsqrtf((float)max(d2, 1));
        ndst[i + 3] = rsqrtf((float)max(d3, 1));
        ndst[i + 4] = rsqrtf((float)max(d4, 1));
        nsrc[i] = rsqrtf((float)max(o0, 1));
        nsrc[i + 1] = rsqrtf((float)max(o1, 1));
        nsrc[i + 2] = rsqrtf((float)max(o2, 1));
        nsrc[i + 3] = rsqrtf((float)max(o3, 1));
        nsrc[i + 4] = rsqrtf((float)max(o4, 1));
    }
    for (; i < e; i++) {
        int d = degi[i];
        s0 += d;
        ndst[i] = rsqrtf((float)max(d, 1));
        nsrc[i] = rsqrtf((float)max(dego[i], 1));
    }
    tsum[t] = s0 + s1 + s2 + s3 + s4;
}

// merged scan + offset writeback: each of 8 blocks redundantly scans the 2048
// partials in smem, then writes off/cur for its own 256 chunks.
__global__ void scanwrite_kernel(const int* __restrict__ degi,
                                 const int* __restrict__ tsum,
                                 int* off, int* cur, int N) {
    __shared__ int sdata[SCAN_T];
    __shared__ int wsum[8];
    const int i = threadIdx.x;   // 0..255

    #pragma unroll
    for (int k = 0; k < 8; k++) sdata[k * 256 + i] = tsum[k * 256 + i];
    __syncthreads();

    // thread i owns partials [i*8, i*8+8)
    int base = i * 8;
    int loc[8];
    int p = 0;
    #pragma unroll
    for (int k = 0; k < 8; k++) {
        loc[k] = p;
        p += sdata[base + k];
    }
    // scan p across 256 threads
    int lane = i & 31, wid = i >> 5;
    int inc = p;
    #pragma unroll
    for (int d = 1; d < 32; d <<= 1) {
        int u = __shfl_up_sync(0xffffffffu, inc, d);
        if (lane >= d) inc += u;
    }
    if (lane == 31) wsum[wid] = inc;
    __syncthreads();
    if (i == 0) {
        int run = 0;
        #pragma unroll
        for (int k = 0; k < 8; k++) {
            int v = wsum[k];
            wsum[k] = run;
            run += v;
        }
    }
    __syncthreads();
    int texcl = inc - p + wsum[wid];   // exclusive prefix of this thread's group
    #pragma unroll
    for (int k = 0; k < 8; k++) sdata[base + k] = texcl + loc[k];
    __syncthreads();

    // this block writes chunks for global ids [blockIdx*256, +256)
    int g = blockIdx.x * 256 + i;
    int chunk = (N + SCAN_T - 1) / SCAN_T;
    int b = g * chunk, e = min(b + chunk, N);
    int run = sdata[g];
    for (int idx = b; idx < e; idx++) {
        off[idx] = run;
        cur[idx] = run;
        run += degi[idx];
    }
    if (g == SCAN_T - 1) off[N] = run;
}

// 8 edges per thread: 8 independent ATOMG returns in flight.
__global__ void fill_kernel(const int* __restrict__ src, const int* __restrict__ dst,
                            int* cur, int* csr, int E) {
    int i = blockIdx.x * blockDim.x + threadIdx.x;
    int E8 = E >> 3;
    if (i < E8) {
        int4 sa = __ldg((const int4*)src + 2 * i);
        int4 sb = __ldg((const int4*)src + 2 * i + 1);
        int4 da = __ldg((const int4*)dst + 2 * i);
        int4 db = __ldg((const int4*)dst + 2 * i + 1);
        int p0 = atomicAdd(&cur[da.x], 1);
        int p1 = atomicAdd(&cur[da.y], 1);
        int p2 = atomicAdd(&cur[da.z], 1);
        int p3 = atomicAdd(&cur[da.w], 1);
        int p4 = atomicAdd(&cur[db.x], 1);
        int p5 = atomicAdd(&cur[db.y], 1);
        int p6 = atomicAdd(&cur[db.z], 1);
        int p7 = atomicAdd(&cur[db.w], 1);
        csr[p0] = sa.x;
        csr[p1] = sa.y;
        csr[p2] = sa.z;
        csr[p3] = sa.w;
        csr[p4] = sb.x;
        csr[p5] = sb.y;
        csr[p6] = sb.z;
        csr[p7] = sb.w;
    }
    if (i == 0) {
        for (int e = E8 << 3; e < E; e++) {
            int p = atomicAdd(&cur[dst[e]], 1);
            csr[p] = src[e];
        }
    }
}

// ---------------- pull SpMM: agg[d] = fp16( ndst[d] * sum_{s in in(d)} h[s] ) -----------
__global__ void pull_kernel(const int* __restrict__ off, const int* __restrict__ csr,
                            const float* __restrict__ ndst,
                            const uint2* __restrict__ h2, uint2* __restrict__ agg2, int N) {
    int w = (blockIdx.x * blockDim.x + threadIdx.x) >> 5;
    int lane = threadIdx.x & 31;
    if (w >= N) return;
    int beg = __ldg(&off[w]);
    int end = __ldg(&off[w + 1]);

    unsigned long long a0 = pack2(0.f, 0.f), a1 = a0, b0 = a0, b1 = a0;

    int j = beg;
    for (; j + 8 <= end; j += 8) {
        int s0 = __ldg(&csr[j]);
        int s1 = __ldg(&csr[j + 1]);
        int s2 = __ldg(&csr[j + 2]);
        int s3 = __ldg(&csr[j + 3]);
        int s4 = __ldg(&csr[j + 4]);
        int s5 = __ldg(&csr[j + 5]);
        int s6 = __ldg(&csr[j + 6]);
        int s7 = __ldg(&csr[j + 7]);
        uint2 v0 = __ldg(&h2[(long)s0 * 32 + lane]);
        uint2 v1 = __ldg(&h2[(long)s1 * 32 + lane]);
        uint2 v2 = __ldg(&h2[(long)s2 * 32 + lane]);
        uint2 v3 = __ldg(&h2[(long)s3 * 32 + lane]);
        uint2 v4 = __ldg(&h2[(long)s4 * 32 + lane]);
        uint2 v5 = __ldg(&h2[(long)s5 * 32 + lane]);
        uint2 v6 = __ldg(&h2[(long)s6 * 32 + lane]);
        uint2 v7 = __ldg(&h2[(long)s7 * 32 + lane]);
        acc_h2(a0, a1, v0);
        acc_h2(b0, b1, v1);
        acc_h2(a0, a1, v2);
        acc_h2(b0, b1, v3);
        acc_h2(a0, a1, v4);
        acc_h2(b0, b1, v5);
        acc_h2(a0, a1, v6);
        acc_h2(b0, b1, v7);
    }
    for (; j < end; j++) {
        int s = __ldg(&csr[j]);
        acc_h2(a0, a1, __ldg(&h2[(long)s * 32 + lane]));
    }
    addx2(a0, b0);
    addx2(a1, b1);

    float nd = __ldg(&ndst[w]);
    unsigned long long nn = pack2(nd, nd);
    mulx2(a0, nn);
    mulx2(a1, nn);
    float4 o;
    unpack2(a0, o.x, o.y);
    unpack2(a1, o.z, o.w);
    __half2 p0 = __floats2half2_rn(o.x, o.y);
    __half2 p1 = __floats2half2_rn(o.z, o.w);
    uint2 st;
    st.x = *(uint32_t*)&p0;
    st.y = *(uint32_t*)&p1;
    agg2[(long)w * 32 + lane] = st;
}

// ---------------- HMMA GEMM: out = relu(X @ W + bias) * postscale ----------------
template <int KTILES, bool FP32IN, bool HALF_OUT>
__global__ void __launch_bounds__(256, 2)
gemm_mma_kernel(const void* __restrict__ Xv, const uint2* __restrict__ Wfrag,
                const float* __restrict__ B, const float* __restrict__ postscale,
                void* __restrict__ outv, int n) {
    constexpr int XPADH = KTILES * 16 + 8;
    constexpr int C4 = KTILES * 4;
    extern __shared__ char smraw[];
    __half* x_sh = (__half*)smraw;
    uint2* w_sh = (uint2*)(smraw + 128 * XPADH * 2);

    const int tx = threadIdx.x;
    const int row0 = blockIdx.x * 128;

    #pragma unroll
    for (int i = tx; i < KTILES * 512; i += 256) w_sh[i] = __ldg(&Wfrag[i]);

    #pragma unroll
    for (int i = tx; i < 128 * C4; i += 256) {
        int r = i / C4, c = i % C4;
        int gr = row0 + r;
        if (gr >= n) gr = n - 1;
        uint2 v;
        if (FP32IN) {
            float4 f = __ldg((const float4*)Xv + (long)gr * C4 + c);
            __half2 h0 = __floats2half2_rn(f.x, f.y);
            __half2 h1 = __floats2half2_rn(f.z, f.w);
            v.x = *(uint32_t*)&h0;
            v.y = *(uint32_t*)&h1;
        } else {
            v = __ldg((const uint2*)Xv + (long)gr * C4 + c);
        }
        *(uint2*)&x_sh[r * XPADH + c * 4] = v;
    }
    __syncthreads();

    const int w = tx >> 5;
    const int lane = tx & 31;
    const int rq = lane >> 2;
    const int kq = (lane & 3) * 2;

    float c[16][4];
    #pragma unroll
    for (int nt = 0; nt < 16; nt++)
        #pragma unroll
        for (int q = 0; q < 4; q++) c[nt][q] = 0.0f;

    #pragma unroll
    for (int kt = 0; kt < KTILES; kt++) {
        const __half* arow0 = &x_sh[(w * 16 + rq) * XPADH + kt * 16 + kq];
        const __half* arow1 = arow0 + 8 * XPADH;
        uint32_t a0 = *(const uint32_t*)arow0;
        uint32_t a1 = *(const uint32_t*)arow1;
        uint32_t a2 = *(const uint32_t*)(arow0 + 8);
        uint32_t a3 = *(const uint32_t*)(arow1 + 8);
        #pragma unroll
        for (int nt = 0; nt < 16; nt++) {
            uint2 b = w_sh[(kt * 16 + nt) * 32 + lane];
            hmma(c[nt], a0, a1, a2, a3, b.x, b.y);
        }
    }

    int r0 = row0 + w * 16 + rq;
    int r1 = r0 + 8;
    float sc0 = 1.0f, sc1 = 1.0f;
    if (postscale) {
        if (r0 < n) sc0 = __ldg(&postscale[r0]);
        if (r1 < n) sc1 = __ldg(&postscale[r1]);
    }
    #pragma unroll
    for (int nt = 0; nt < 16; nt++) {
        int col = nt * 8 + kq;
        float2 bv = *(const float2*)&B[col];
        float o00 = fmaxf(c[nt][0] + bv.x, 0.0f) * sc0;
        float o01 = fmaxf(c[nt][1] + bv.y, 0.0f) * sc0;
        float o10 = fmaxf(c[nt][2] + bv.x, 0.0f) * sc1;
        float o11 = fmaxf(c[nt][3] + bv.y, 0.0f) * sc1;
        if (HALF_OUT) {
            if (r0 < n) {
                __half2 p = __floats2half2_rn(o00, o01);
                *(uint32_t*)((__half*)outv + (long)r0 * 128 + col) = *(uint32_t*)&p;
            }
            if (r1 < n) {
                __half2 p = __floats2half2_rn(o10, o11);
                *(uint32_t*)((__half*)outv + (long)r1 * 128 + col) = *(uint32_t*)&p;
            }
        } else {
            if (r0 < n)
                *(float2*)((float*)outv + (long)r0 * 128 + col) = make_float2(o00, o01);
            if (r1 < n)
                *(float2*)((float*)outv + (long)r1 * 128 + col) = make_float2(o10, o11);
        }
    }
}

extern "C" void kernel_launch(void* const* d_in, const int* in_sizes, int n_in,
                              void* d_out, int out_size) {
    const float* x_raw = (const float*)d_in[0];
    const int*   src   = (const int*)d_in[1];
    const int*   dst   = (const int*)d_in[2];
    const float* Wp    = (const float*)d_in[3];
    const float* bp    = (const float*)d_in[4];
    const float* Wl    = (const float*)d_in[5];
    const float* bl    = (const float*)d_in[6];
    float* out = (float*)d_out;

    const int N = in_sizes[0] / 64;
    const int E = in_sizes[1];

    __half *h, *agg;
    float *nsrc, *ndst;
    int *dego, *degi, *off, *cur, *csr, *tsum;
    uint2* wfrag;
    cudaGetSymbolAddress((void**)&h, g_h);
    cudaGetSymbolAddress((void**)&agg, g_agg);
    cudaGetSymbolAddress((void**)&nsrc, g_nsrc);
    cudaGetSymbolAddress((void**)&ndst, g_ndst);
    cudaGetSymbolAddress((void**)&dego, g_dego);
    cudaGetSymbolAddress((void**)&degi, g_degi);
    cudaGetSymbolAddress((void**)&off, g_off);
    cudaGetSymbolAddress((void**)&cur, g_cur);
    cudaGetSymbolAddress((void**)&csr, g_csr);
    cudaGetSymbolAddress((void**)&tsum, g_tsum);
    cudaGetSymbolAddress((void**)&wfrag, g_wfrag);

    const int MMA_SMEM128 = 128 * 136 * 2 + 4096 * 8;
    const int MMA_SMEM64 = 128 * 72 * 2 + 2048 * 8;
    cudaFuncSetAttribute((const void*)gemm_mma_kernel<8, false, true>,
                         cudaFuncAttributeMaxDynamicSharedMemorySize, MMA_SMEM128);
    cudaFuncSetAttribute((const void*)gemm_mma_kernel<8, false, false>,
                         cudaFuncAttributeMaxDynamicSharedMemorySize, MMA_SMEM128);
    cudaFuncSetAttribute((const void*)gemm_mma_kernel<4, true, true>,
                         cudaFuncAttributeMaxDynamicSharedMemorySize, MMA_SMEM64);

    // 0) weight frags + zero degree counters (merged)
    prep_kernel<<<(3 * 4096 + 2048 + 255) / 256, 256>>>(
        Wp, Wl, wfrag, (int4*)dego, (int4*)degi);

    // 1) degrees -> norms + CSR(by dst); merged scan pipeline
    const int E8 = E >> 3;
    degree_kernel<<<(E8 + 255) / 256, 256>>>(src, dst, dego, degi, E);
    partsum_norm_kernel<<<SCAN_T / 256, 256>>>(degi, dego, tsum, nsrc, ndst, N);
    scanwrite_kernel<<<SCAN_T / 256, 256>>>(degi, tsum, off, cur, N);
    fill_kernel<<<(E8 + 255) / 256, 256>>>(src, dst, cur, csr, E);

    // 2) h = fp16( relu(x_raw @ Wp + bp) * norm_src )  — HMMA, K=64
    const int mma_blocks = (N + 127) / 128;
    gemm_mma_kernel<4, true, true><<<mma_blocks, 256, MMA_SMEM64>>>(
        x_raw, wfrag + 12288, bp, nsrc, h, N);

    // 3) layers: pull then HMMA GEMM
    const int pull_blocks = (N * 32 + 255) / 256;
    for (int l = 0; l < 3; l++) {
        pull_kernel<<<pull_blocks, 256>>>(off, csr, ndst, (const uint2*)h, (uint2*)agg, N);
        const uint2* wf = wfrag + (long)l * 4096;
        const float* bcur = bl + (long)l * 128;
        if (l == 2) {
            gemm_mma_kernel<8, false, false><<<mma_blocks, 256, MMA_SMEM128>>>(
                (const void*)agg, wf, bcur, nullptr, out, N);
        } else {
            gemm_mma_kernel<8, false, true><<<mma_blocks, 256, MMA_SMEM128>>>(
                (const void*)agg, wf, bcur, nsrc, h, N);
        }
    }
}